// round 13
// baseline (speedup 1.0000x reference)
#include <cuda_runtime.h>
#include <cuda_fp16.h>
#include <cstdint>

#define Hd     1536
#define FOURH  6144
#define NS     1008      // (T-1)*B = 63*16 sequential steps
#define CHUNKS 6         // 1536 / 256
#define SC     3         // chunks cached in smem per warp

// ---------------- static device scratch ----------------
__device__ float  g_xpre[(size_t)NS * FOURH];       // layer-0 input projection
__device__ __align__(16) __half g_Whh0h[(size_t)FOURH * Hd];  // fp16, lane-permuted
__device__ __align__(16) __half g_Wih1h[(size_t)FOURH * Hd];
__device__ __align__(16) __half g_Whh1h[(size_t)FOURH * Hd];
__device__ float  g_h0[2][Hd];
__device__ float  g_h1[2][Hd];
__device__ float  g_pa[2][FOURH];
__device__ unsigned int g_arrive[1024];             // per-block arrival flags
// Reset to zero by the prologue each launch -> barrier state is launch-local.

// dyn smem: [ sh0:1536 f32 | sh1:1536 f32 | wcache: 32 warps * 6KB ]
#define WC_PER_WARP (SC * 4 * 256)                 // halves
#define SMEM_BYTES  (2 * Hd * 4 + 32 * WC_PER_WARP * 2)

// ---------------- all-scan flag barrier (no atomics, no central releaser) -----------
// Arrival: per-block flag STG (distinct addresses, parallel). Release: EVERY
// block's warp 0 scans all NB flags itself -> single L2 hop after last arrival.
__device__ __forceinline__ void grid_barrier(int NB, unsigned int target) {
    __syncthreads();
    if (threadIdx.x < 32) {
        if (threadIdx.x == 0) {
            __threadfence();
            ((volatile unsigned int*)g_arrive)[blockIdx.x] = target;
        }
        bool done;
        do {
            done = true;
            for (int i = threadIdx.x; i < NB; i += 32) {
                if (((volatile unsigned int*)g_arrive)[i] < target) done = false;
            }
        } while (!__all_sync(0xffffffffu, done));
        if (threadIdx.x == 0) __threadfence();
    }
    __syncthreads();
}

__device__ __forceinline__ float wred(float v) {
    v += __shfl_xor_sync(0xffffffffu, v, 16);
    v += __shfl_xor_sync(0xffffffffu, v, 8);
    v += __shfl_xor_sync(0xffffffffu, v, 4);
    v += __shfl_xor_sync(0xffffffffu, v, 2);
    v += __shfl_xor_sync(0xffffffffu, v, 1);
    return v;
}

__device__ __forceinline__ float sigm(float x) { return 1.0f / (1.0f + expf(-x)); }

// ---------------- merged prologue: barrier reset + weight convert + x_pre0 GEMM ------
#define CVT_BLOCKS 110592   // 3*FOURH*Hd / 256
__global__ void prologue(const float* __restrict__ batch,
                         const float* __restrict__ Wih0,
                         const float* __restrict__ bih0,
                         const float* __restrict__ bhh0,
                         const float* __restrict__ Whh0,
                         const float* __restrict__ Wih1,
                         const float* __restrict__ Whh1) {
    __shared__ float Xs[64][33];
    __shared__ float Ws[64][33];

    // block 0 resets barrier flags for the upcoming lstm_seq launch
    if (blockIdx.x == 0) {
        for (int i = threadIdx.x; i < 1024; i += 256) g_arrive[i] = 0u;
    }

    if (blockIdx.x < CVT_BLOCKS) {
        // dst p = chunk*256 + lane*8 + e  <-  src chunk*256 + e*32 + lane
        size_t idx = (size_t)blockIdx.x * 256 + threadIdx.x;
        const size_t per = (size_t)FOURH * Hd;
        int which = (int)(idx / per);
        size_t rem = idx % per;
        size_t r = rem / Hd;
        int p = (int)(rem % Hd);
        int chunk = p >> 8, q = p & 255, lane = q >> 3, e = q & 7;
        int srcp = chunk * 256 + e * 32 + lane;
        const float* src = (which == 0) ? Whh0 : (which == 1) ? Wih1 : Whh1;
        __half* dst = (which == 0) ? g_Whh0h : (which == 1) ? g_Wih1h : g_Whh1h;
        dst[r * Hd + p] = __float2half(src[r * Hd + srcp]);
        return;
    }

    int bid = blockIdx.x - CVT_BLOCKS;          // 0..1535
    int nb = (bid % (FOURH / 64)) * 64;
    int mb = (bid / (FOURH / 64)) * 64;
    int tid = threadIdx.x;
    int tx = tid % 16, ty = tid / 16;

    float acc[4][4];
#pragma unroll
    for (int i = 0; i < 4; i++)
#pragma unroll
        for (int jj = 0; jj < 4; jj++) acc[i][jj] = 0.0f;

    for (int k0 = 0; k0 < 256; k0 += 32) {
#pragma unroll
        for (int i = 0; i < 8; i++) {
            int idx = tid + i * 256;
            int r = idx >> 5, kk = idx & 31;
            int m = mb + r;
            float v = 0.0f;
            if (m < NS) {
                int ei = m >> 4, bb = m & 15;
                v = batch[(size_t)bb * (64 * 256) + (size_t)(ei + 1) * 256 + (k0 + kk)];
            }
            Xs[r][kk] = v;
        }
#pragma unroll
        for (int i = 0; i < 8; i++) {
            int idx = tid + i * 256;
            int r = idx >> 5, kk = idx & 31;
            Ws[r][kk] = Wih0[(size_t)(nb + r) * 256 + (k0 + kk)];
        }
        __syncthreads();
#pragma unroll
        for (int kk = 0; kk < 32; kk++) {
            float xv[4], wv[4];
#pragma unroll
            for (int i = 0; i < 4; i++) xv[i] = Xs[ty * 4 + i][kk];
#pragma unroll
            for (int jj = 0; jj < 4; jj++) wv[jj] = Ws[tx * 4 + jj][kk];
#pragma unroll
            for (int i = 0; i < 4; i++)
#pragma unroll
                for (int jj = 0; jj < 4; jj++) acc[i][jj] += xv[i] * wv[jj];
        }
        __syncthreads();
    }
#pragma unroll
    for (int i = 0; i < 4; i++) {
        int m = mb + ty * 4 + i;
        if (m >= NS) continue;
#pragma unroll
        for (int jj = 0; jj < 4; jj++) {
            int n = nb + tx * 4 + jj;
            g_xpre[(size_t)m * FOURH + n] = acc[i][jj] + bih0[n] + bhh0[n];
        }
    }
}

// ---------------- one 256-wide chunk: 4 gate rows (R5 fp32 path) ----------------
__device__ __forceinline__ void mv_chunk4(const __half* p0, const __half* p1,
                                          const __half* p2, const __half* p3,
                                          const float* __restrict__ sh, int kbase,
                                          int lane, float acc[4]) {
    float hv0 = sh[kbase + lane +   0], hv1 = sh[kbase + lane +  32];
    float hv2 = sh[kbase + lane +  64], hv3 = sh[kbase + lane +  96];
    float hv4 = sh[kbase + lane + 128], hv5 = sh[kbase + lane + 160];
    float hv6 = sh[kbase + lane + 192], hv7 = sh[kbase + lane + 224];
#pragma unroll
    for (int t = 0; t < 4; t++) {
        const __half* rp = (t == 0) ? p0 : (t == 1) ? p1 : (t == 2) ? p2 : p3;
        uint4 u = *(const uint4*)(rp + lane * 8);
        const __half2* h2 = (const __half2*)&u;
        float2 f0 = __half22float2(h2[0]);
        float2 f1 = __half22float2(h2[1]);
        float2 f2 = __half22float2(h2[2]);
        float2 f3 = __half22float2(h2[3]);
        acc[t] += f0.x * hv0 + f0.y * hv1 + f1.x * hv2 + f1.y * hv3
                + f2.x * hv4 + f2.y * hv5 + f3.x * hv6 + f3.y * hv7;
    }
}

__device__ __forceinline__ void mv4_hybrid(const __half* __restrict__ scache,
                                           const __half* __restrict__ gW, int j,
                                           const float* __restrict__ sh, int lane,
                                           float acc[4]) {
    const __half* r0 = gW + (size_t)(0 * Hd + j) * Hd;
    const __half* r1 = gW + (size_t)(1 * Hd + j) * Hd;
    const __half* r2 = gW + (size_t)(2 * Hd + j) * Hd;
    const __half* r3 = gW + (size_t)(3 * Hd + j) * Hd;
#pragma unroll
    for (int cc = SC; cc < CHUNKS; cc++) {
        mv_chunk4(r0 + cc * 256, r1 + cc * 256, r2 + cc * 256, r3 + cc * 256,
                  sh, cc * 256, lane, acc);
    }
#pragma unroll
    for (int cc = 0; cc < SC; cc++) {
        const __half* base = scache + cc * 4 * 256;
        mv_chunk4(base + 0 * 256, base + 1 * 256, base + 2 * 256, base + 3 * 256,
                  sh, cc * 256, lane, acc);
    }
}

// ---------------- persistent sequential LSTM ----------------
__global__ __launch_bounds__(1024, 1)
void lstm_seq(const float* __restrict__ bih1,
              const float* __restrict__ bhh1,
              float* __restrict__ out,
              int G) {
    extern __shared__ unsigned char dynsmem[];
    float*  sh0    = (float*)dynsmem;               // 1536 f32
    float*  sh1    = sh0 + Hd;                      // 1536 f32
    __half* wcache = (__half*)(sh1 + Hd);

    int tid  = threadIdx.x;
    int b    = blockIdx.x;
    int warp = tid >> 5;
    int lane = tid & 31;

    unsigned int bar_n = 0;   // launch-local: prologue zeroed the flags

    for (int i = tid; i < Hd; i += 1024) {
        g_h0[0][i] = 0.0f; g_h0[1][i] = 0.0f;
        g_h1[0][i] = 0.0f; g_h1[1][i] = 0.0f;
    }
    for (int i = tid + b * 1024; i < FOURH; i += 1024 * G) {
        g_pa[0][i] = 0.0f; g_pa[1][i] = 0.0f;
    }

    int u = warp * G + b;
    bool isL0 = (u < Hd);
    bool isA  = (u >= Hd)     && (u < 2 * Hd);
    bool isB  = (u >= 2 * Hd) && (u < 3 * Hd);
    bool active = isL0 || isA || isB;
    int j = isL0 ? u : isA ? (u - Hd) : (u - 2 * Hd);

    const __half* gW = isL0 ? g_Whh0h : isA ? g_Wih1h : g_Whh1h;
    __half* scache = wcache + (size_t)warp * WC_PER_WARP;

    if (active) {
#pragma unroll
        for (int cc = 0; cc < SC; cc++) {
#pragma unroll
            for (int t = 0; t < 4; t++) {
                const __half* src = gW + (size_t)(t * Hd + j) * Hd + cc * 256 + lane * 8;
                __half* dst = scache + (cc * 4 + t) * 256 + lane * 8;
                *(uint4*)dst = *(const uint4*)src;
            }
        }
    }

    float bi = 0.f, bf = 0.f, bg = 0.f, bo = 0.f;
    if (isB) {
        bi = bih1[0 * Hd + j] + bhh1[0 * Hd + j];
        bf = bih1[1 * Hd + j] + bhh1[1 * Hd + j];
        bg = bih1[2 * Hd + j] + bhh1[2 * Hd + j];
        bo = bih1[3 * Hd + j] + bhh1[3 * Hd + j];
    }

    grid_barrier(G, ++bar_n);

    float c = 0.0f, h = 0.0f;   // register-resident cell state

    for (int it = 0; it <= NS + 1; ++it) {
        int rp = (it + 1) & 1;   // read parity
        int wp = it & 1;         // write parity

        // ---- hoisted loads independent of staged h ----
        float xpi = 0.f, xpf = 0.f, xpg = 0.f, xpo = 0.f;
        if (isL0 && it < NS) {
            const float* xp = g_xpre + (size_t)it * FOURH;
            xpi = xp[0 * Hd + j];
            xpf = xp[1 * Hd + j];
            xpg = xp[2 * Hd + j];
            xpo = xp[3 * Hd + j];
        }
        float pai = 0.f, paf = 0.f, pag = 0.f, pao = 0.f;
        if (isB && it >= 2) {
            volatile const float* pa = g_pa[rp];
            pai = pa[0 * Hd + j];
            paf = pa[1 * Hd + j];
            pag = pa[2 * Hd + j];
            pao = pa[3 * Hd + j];
        }

        // ---- stage previous h vectors into smem (fp32) ----
        {
            volatile const float* vh0 = g_h0[rp];
            volatile const float* vh1 = g_h1[rp];
            for (int i = tid; i < Hd; i += 1024) {
                sh0[i] = vh0[i];
                sh1[i] = vh1[i];
            }
        }
        __syncthreads();

        if (isL0) {
            if (it < NS) {
                float acc[4] = {0.f, 0.f, 0.f, 0.f};
                mv4_hybrid(scache, gW, j, sh0, lane, acc);
                float pi = wred(acc[0]) + xpi;
                float pf = wred(acc[1]) + xpf;
                float pg = wred(acc[2]) + xpg;
                float po = wred(acc[3]) + xpo;
                c = sigm(pf) * c + sigm(pi) * tanhf(pg);
                h = sigm(po) * tanhf(c);
                if (lane == 0) ((volatile float*)g_h0[wp])[j] = h;
            }
        } else if (isA) {
            if (it >= 1 && it <= NS) {
                float acc[4] = {0.f, 0.f, 0.f, 0.f};
                mv4_hybrid(scache, gW, j, sh0, lane, acc);
                float pi = wred(acc[0]);
                float pf = wred(acc[1]);
                float pg = wred(acc[2]);
                float po = wred(acc[3]);
                if (lane == 0) {
                    volatile float* pa = g_pa[wp];
                    pa[0 * Hd + j] = pi;
                    pa[1 * Hd + j] = pf;
                    pa[2 * Hd + j] = pg;
                    pa[3 * Hd + j] = po;
                }
            }
        } else if (isB) {
            if (it >= 2) {
                float acc[4] = {0.f, 0.f, 0.f, 0.f};
                mv4_hybrid(scache, gW, j, sh1, lane, acc);
                float pi = wred(acc[0]) + pai + bi;
                float pf = wred(acc[1]) + paf + bf;
                float pg = wred(acc[2]) + pag + bg;
                float po = wred(acc[3]) + pao + bo;
                if (lane == 0) {
                    c = sigm(pf) * c + sigm(pi) * tanhf(pg);
                    h = sigm(po) * tanhf(c);
                    ((volatile float*)g_h1[wp])[j] = h;
                }
            }
        }

        grid_barrier(G, ++bar_n);
    }

    // out layout: [h0 | h1 | c0 | c1]
    if (lane == 0) {
        if (isL0) { out[j] = h;      out[2 * Hd + j] = c; }
        if (isB)  { out[Hd + j] = h; out[3 * Hd + j] = c; }
    }
}

// ---------------- launch ----------------
extern "C" void kernel_launch(void* const* d_in, const int* in_sizes, int n_in,
                              void* d_out, int out_size) {
    const float* batch = (const float*)d_in[0];
    const float* Wih0  = (const float*)d_in[1];
    const float* Whh0  = (const float*)d_in[2];
    const float* bih0  = (const float*)d_in[3];
    const float* bhh0  = (const float*)d_in[4];
    const float* Wih1  = (const float*)d_in[5];
    const float* Whh1  = (const float*)d_in[6];
    const float* bih1  = (const float*)d_in[7];
    const float* bhh1  = (const float*)d_in[8];
    float* out = (float*)d_out;

    int dev = 0;
    cudaGetDevice(&dev);
    int G = 0;
    cudaDeviceGetAttribute(&G, cudaDevAttrMultiProcessorCount, dev);
    if (G <= 0) G = 148;
    if (G > 1024) G = 1024;

    static int smem_set = 0;
    if (!smem_set) {
        cudaFuncSetAttribute(lstm_seq, cudaFuncAttributeMaxDynamicSharedMemorySize,
                             SMEM_BYTES);
        smem_set = 1;
    }

    int pro_blocks = CVT_BLOCKS + (FOURH / 64) * ((NS + 63) / 64);
    prologue<<<pro_blocks, 256>>>(batch, Wih0, bih0, bhh0, Whh0, Wih1, Whh1);

    lstm_seq<<<G, 1024, SMEM_BYTES>>>(bih1, bhh1, out, G);
}

// round 14
// speedup vs baseline: 1.8269x; 1.8269x over previous
#include <cuda_runtime.h>
#include <cuda_fp16.h>
#include <cstdint>

#define Hd     1536
#define FOURH  6144
#define NS     1008      // (T-1)*B = 63*16 sequential steps
#define CHUNKS 6         // 1536 / 256
#define SC     3         // chunks cached in smem per warp

// ---------------- static device scratch ----------------
__device__ float  g_xpre[(size_t)NS * FOURH];       // layer-0 input projection
__device__ __align__(16) __half g_Whh0h[(size_t)FOURH * Hd];  // fp16, lane-permuted
__device__ __align__(16) __half g_Wih1h[(size_t)FOURH * Hd];
__device__ __align__(16) __half g_Whh1h[(size_t)FOURH * Hd];
__device__ float  g_h0[2][Hd];
__device__ float  g_h1[2][Hd];
__device__ float  g_pa[2][FOURH];
// hierarchical barrier state (monotonic within a launch; prologue zeroes it)
__device__ __align__(256) unsigned int g_cnt1[8 * 64];  // level-1 counters, 256B apart
__device__ unsigned int g_cnt2 = 0;                     // level-2 counter
__device__ unsigned int g_gen  = 0;                     // release word (single-word poll)

// dyn smem: [ sh0:1536 f32 | sh1:1536 f32 | wcache: 32 warps * 6KB ]
#define WC_PER_WARP (SC * 4 * 256)                 // halves
#define SMEM_BYTES  (2 * Hd * 4 + 32 * WC_PER_WARP * 2)

// ---------------- hierarchical grid barrier ----------------
// Arrival: block b -> counter (b&7); 8 counters on distinct LTS slices take the
// atomics in parallel (~19 serialized each instead of 152). Group-last (exact,
// from atomicAdd return) bumps level-2; 8th group releases via single-word g_gen.
// Release/poll identical to the proven R5 path. Monotonic: barrier #n waits for
// g_gen >= n; prologue zeroes all state each launch.
__device__ __forceinline__ void grid_barrier(int NB, unsigned int n) {
    __syncthreads();
    if (threadIdx.x == 0) {
        __threadfence();
        int cgrp = blockIdx.x & 7;
        unsigned int gsz = ((unsigned int)(NB - cgrp) + 7u) >> 3;  // blocks in group
        unsigned int a = atomicAdd(&g_cnt1[cgrp * 64], 1u);
        if (a == n * gsz - 1u) {                 // last of this group, barrier n
            unsigned int a2 = atomicAdd(&g_cnt2, 1u);
            if (a2 == n * 8u - 1u) {             // last group overall
                __threadfence();
                *(volatile unsigned int*)&g_gen = n;
            }
        }
        while (*(volatile unsigned int*)&g_gen < n) { }
        __threadfence();
    }
    __syncthreads();
}

__device__ __forceinline__ float wred(float v) {
    v += __shfl_xor_sync(0xffffffffu, v, 16);
    v += __shfl_xor_sync(0xffffffffu, v, 8);
    v += __shfl_xor_sync(0xffffffffu, v, 4);
    v += __shfl_xor_sync(0xffffffffu, v, 2);
    v += __shfl_xor_sync(0xffffffffu, v, 1);
    return v;
}

__device__ __forceinline__ float sigm(float x) { return 1.0f / (1.0f + expf(-x)); }

// ---------------- merged prologue: barrier reset + weight convert + x_pre0 GEMM ------
#define CVT_BLOCKS 110592   // 3*FOURH*Hd / 256
__global__ void prologue(const float* __restrict__ batch,
                         const float* __restrict__ Wih0,
                         const float* __restrict__ bih0,
                         const float* __restrict__ bhh0,
                         const float* __restrict__ Whh0,
                         const float* __restrict__ Wih1,
                         const float* __restrict__ Whh1) {
    __shared__ float Xs[64][33];
    __shared__ float Ws[64][33];

    // block 0 resets barrier state for the upcoming lstm_seq launch
    // (prologue completes fully before lstm_seq starts: stream-ordered)
    if (blockIdx.x == 0) {
        for (int i = threadIdx.x; i < 8 * 64; i += 256) g_cnt1[i] = 0u;
        if (threadIdx.x == 0) { g_cnt2 = 0u; g_gen = 0u; }
    }

    if (blockIdx.x < CVT_BLOCKS) {
        // dst p = chunk*256 + lane*8 + e  <-  src chunk*256 + e*32 + lane
        size_t idx = (size_t)blockIdx.x * 256 + threadIdx.x;
        const size_t per = (size_t)FOURH * Hd;
        int which = (int)(idx / per);
        size_t rem = idx % per;
        size_t r = rem / Hd;
        int p = (int)(rem % Hd);
        int chunk = p >> 8, q = p & 255, lane = q >> 3, e = q & 7;
        int srcp = chunk * 256 + e * 32 + lane;
        const float* src = (which == 0) ? Whh0 : (which == 1) ? Wih1 : Whh1;
        __half* dst = (which == 0) ? g_Whh0h : (which == 1) ? g_Wih1h : g_Whh1h;
        dst[r * Hd + p] = __float2half(src[r * Hd + srcp]);
        return;
    }

    int bid = blockIdx.x - CVT_BLOCKS;          // 0..1535
    int nb = (bid % (FOURH / 64)) * 64;
    int mb = (bid / (FOURH / 64)) * 64;
    int tid = threadIdx.x;
    int tx = tid % 16, ty = tid / 16;

    float acc[4][4];
#pragma unroll
    for (int i = 0; i < 4; i++)
#pragma unroll
        for (int jj = 0; jj < 4; jj++) acc[i][jj] = 0.0f;

    for (int k0 = 0; k0 < 256; k0 += 32) {
#pragma unroll
        for (int i = 0; i < 8; i++) {
            int idx = tid + i * 256;
            int r = idx >> 5, kk = idx & 31;
            int m = mb + r;
            float v = 0.0f;
            if (m < NS) {
                int ei = m >> 4, bb = m & 15;
                v = batch[(size_t)bb * (64 * 256) + (size_t)(ei + 1) * 256 + (k0 + kk)];
            }
            Xs[r][kk] = v;
        }
#pragma unroll
        for (int i = 0; i < 8; i++) {
            int idx = tid + i * 256;
            int r = idx >> 5, kk = idx & 31;
            Ws[r][kk] = Wih0[(size_t)(nb + r) * 256 + (k0 + kk)];
        }
        __syncthreads();
#pragma unroll
        for (int kk = 0; kk < 32; kk++) {
            float xv[4], wv[4];
#pragma unroll
            for (int i = 0; i < 4; i++) xv[i] = Xs[ty * 4 + i][kk];
#pragma unroll
            for (int jj = 0; jj < 4; jj++) wv[jj] = Ws[tx * 4 + jj][kk];
#pragma unroll
            for (int i = 0; i < 4; i++)
#pragma unroll
                for (int jj = 0; jj < 4; jj++) acc[i][jj] += xv[i] * wv[jj];
        }
        __syncthreads();
    }
#pragma unroll
    for (int i = 0; i < 4; i++) {
        int m = mb + ty * 4 + i;
        if (m >= NS) continue;
#pragma unroll
        for (int jj = 0; jj < 4; jj++) {
            int n = nb + tx * 4 + jj;
            g_xpre[(size_t)m * FOURH + n] = acc[i][jj] + bih0[n] + bhh0[n];
        }
    }
}

// ---------------- one 256-wide chunk: 4 gate rows (R5 fp32 path) ----------------
__device__ __forceinline__ void mv_chunk4(const __half* p0, const __half* p1,
                                          const __half* p2, const __half* p3,
                                          const float* __restrict__ sh, int kbase,
                                          int lane, float acc[4]) {
    float hv0 = sh[kbase + lane +   0], hv1 = sh[kbase + lane +  32];
    float hv2 = sh[kbase + lane +  64], hv3 = sh[kbase + lane +  96];
    float hv4 = sh[kbase + lane + 128], hv5 = sh[kbase + lane + 160];
    float hv6 = sh[kbase + lane + 192], hv7 = sh[kbase + lane + 224];
#pragma unroll
    for (int t = 0; t < 4; t++) {
        const __half* rp = (t == 0) ? p0 : (t == 1) ? p1 : (t == 2) ? p2 : p3;
        uint4 u = *(const uint4*)(rp + lane * 8);
        const __half2* h2 = (const __half2*)&u;
        float2 f0 = __half22float2(h2[0]);
        float2 f1 = __half22float2(h2[1]);
        float2 f2 = __half22float2(h2[2]);
        float2 f3 = __half22float2(h2[3]);
        acc[t] += f0.x * hv0 + f0.y * hv1 + f1.x * hv2 + f1.y * hv3
                + f2.x * hv4 + f2.y * hv5 + f3.x * hv6 + f3.y * hv7;
    }
}

__device__ __forceinline__ void mv4_hybrid(const __half* __restrict__ scache,
                                           const __half* __restrict__ gW, int j,
                                           const float* __restrict__ sh, int lane,
                                           float acc[4]) {
    const __half* r0 = gW + (size_t)(0 * Hd + j) * Hd;
    const __half* r1 = gW + (size_t)(1 * Hd + j) * Hd;
    const __half* r2 = gW + (size_t)(2 * Hd + j) * Hd;
    const __half* r3 = gW + (size_t)(3 * Hd + j) * Hd;
#pragma unroll
    for (int cc = SC; cc < CHUNKS; cc++) {
        mv_chunk4(r0 + cc * 256, r1 + cc * 256, r2 + cc * 256, r3 + cc * 256,
                  sh, cc * 256, lane, acc);
    }
#pragma unroll
    for (int cc = 0; cc < SC; cc++) {
        const __half* base = scache + cc * 4 * 256;
        mv_chunk4(base + 0 * 256, base + 1 * 256, base + 2 * 256, base + 3 * 256,
                  sh, cc * 256, lane, acc);
    }
}

// ---------------- persistent sequential LSTM ----------------
__global__ __launch_bounds__(1024, 1)
void lstm_seq(const float* __restrict__ bih1,
              const float* __restrict__ bhh1,
              float* __restrict__ out,
              int G) {
    extern __shared__ unsigned char dynsmem[];
    float*  sh0    = (float*)dynsmem;               // 1536 f32
    float*  sh1    = sh0 + Hd;                      // 1536 f32
    __half* wcache = (__half*)(sh1 + Hd);

    int tid  = threadIdx.x;
    int b    = blockIdx.x;
    int warp = tid >> 5;
    int lane = tid & 31;

    unsigned int bar_n = 0;   // launch-local: prologue zeroed the barrier state

    for (int i = tid; i < Hd; i += 1024) {
        g_h0[0][i] = 0.0f; g_h0[1][i] = 0.0f;
        g_h1[0][i] = 0.0f; g_h1[1][i] = 0.0f;
    }
    for (int i = tid + b * 1024; i < FOURH; i += 1024 * G) {
        g_pa[0][i] = 0.0f; g_pa[1][i] = 0.0f;
    }

    int u = warp * G + b;
    bool isL0 = (u < Hd);
    bool isA  = (u >= Hd)     && (u < 2 * Hd);
    bool isB  = (u >= 2 * Hd) && (u < 3 * Hd);
    bool active = isL0 || isA || isB;
    int j = isL0 ? u : isA ? (u - Hd) : (u - 2 * Hd);

    const __half* gW = isL0 ? g_Whh0h : isA ? g_Wih1h : g_Whh1h;
    __half* scache = wcache + (size_t)warp * WC_PER_WARP;

    if (active) {
#pragma unroll
        for (int cc = 0; cc < SC; cc++) {
#pragma unroll
            for (int t = 0; t < 4; t++) {
                const __half* src = gW + (size_t)(t * Hd + j) * Hd + cc * 256 + lane * 8;
                __half* dst = scache + (cc * 4 + t) * 256 + lane * 8;
                *(uint4*)dst = *(const uint4*)src;
            }
        }
    }

    float bi = 0.f, bf = 0.f, bg = 0.f, bo = 0.f;
    if (isB) {
        bi = bih1[0 * Hd + j] + bhh1[0 * Hd + j];
        bf = bih1[1 * Hd + j] + bhh1[1 * Hd + j];
        bg = bih1[2 * Hd + j] + bhh1[2 * Hd + j];
        bo = bih1[3 * Hd + j] + bhh1[3 * Hd + j];
    }

    grid_barrier(G, ++bar_n);

    float c = 0.0f, h = 0.0f;   // register-resident cell state

    for (int it = 0; it <= NS + 1; ++it) {
        int rp = (it + 1) & 1;   // read parity
        int wp = it & 1;         // write parity

        // ---- hoisted loads independent of staged h ----
        float xpi = 0.f, xpf = 0.f, xpg = 0.f, xpo = 0.f;
        if (isL0 && it < NS) {
            const float* xp = g_xpre + (size_t)it * FOURH;
            xpi = xp[0 * Hd + j];
            xpf = xp[1 * Hd + j];
            xpg = xp[2 * Hd + j];
            xpo = xp[3 * Hd + j];
        }
        float pai = 0.f, paf = 0.f, pag = 0.f, pao = 0.f;
        if (isB && it >= 2) {
            volatile const float* pa = g_pa[rp];
            pai = pa[0 * Hd + j];
            paf = pa[1 * Hd + j];
            pag = pa[2 * Hd + j];
            pao = pa[3 * Hd + j];
        }

        // ---- stage previous h vectors into smem (fp32) ----
        {
            volatile const float* vh0 = g_h0[rp];
            volatile const float* vh1 = g_h1[rp];
            for (int i = tid; i < Hd; i += 1024) {
                sh0[i] = vh0[i];
                sh1[i] = vh1[i];
            }
        }
        __syncthreads();

        if (isL0) {
            if (it < NS) {
                float acc[4] = {0.f, 0.f, 0.f, 0.f};
                mv4_hybrid(scache, gW, j, sh0, lane, acc);
                float pi = wred(acc[0]) + xpi;
                float pf = wred(acc[1]) + xpf;
                float pg = wred(acc[2]) + xpg;
                float po = wred(acc[3]) + xpo;
                c = sigm(pf) * c + sigm(pi) * tanhf(pg);
                h = sigm(po) * tanhf(c);
                if (lane == 0) ((volatile float*)g_h0[wp])[j] = h;
            }
        } else if (isA) {
            if (it >= 1 && it <= NS) {
                float acc[4] = {0.f, 0.f, 0.f, 0.f};
                mv4_hybrid(scache, gW, j, sh0, lane, acc);
                float pi = wred(acc[0]);
                float pf = wred(acc[1]);
                float pg = wred(acc[2]);
                float po = wred(acc[3]);
                if (lane == 0) {
                    volatile float* pa = g_pa[wp];
                    pa[0 * Hd + j] = pi;
                    pa[1 * Hd + j] = pf;
                    pa[2 * Hd + j] = pg;
                    pa[3 * Hd + j] = po;
                }
            }
        } else if (isB) {
            if (it >= 2) {
                float acc[4] = {0.f, 0.f, 0.f, 0.f};
                mv4_hybrid(scache, gW, j, sh1, lane, acc);
                float pi = wred(acc[0]) + pai + bi;
                float pf = wred(acc[1]) + paf + bf;
                float pg = wred(acc[2]) + pag + bg;
                float po = wred(acc[3]) + pao + bo;
                if (lane == 0) {
                    c = sigm(pf) * c + sigm(pi) * tanhf(pg);
                    h = sigm(po) * tanhf(c);
                    ((volatile float*)g_h1[wp])[j] = h;
                }
            }
        }

        grid_barrier(G, ++bar_n);
    }

    // out layout: [h0 | h1 | c0 | c1]
    if (lane == 0) {
        if (isL0) { out[j] = h;      out[2 * Hd + j] = c; }
        if (isB)  { out[Hd + j] = h; out[3 * Hd + j] = c; }
    }
}

// ---------------- launch ----------------
extern "C" void kernel_launch(void* const* d_in, const int* in_sizes, int n_in,
                              void* d_out, int out_size) {
    const float* batch = (const float*)d_in[0];
    const float* Wih0  = (const float*)d_in[1];
    const float* Whh0  = (const float*)d_in[2];
    const float* bih0  = (const float*)d_in[3];
    const float* bhh0  = (const float*)d_in[4];
    const float* Wih1  = (const float*)d_in[5];
    const float* Whh1  = (const float*)d_in[6];
    const float* bih1  = (const float*)d_in[7];
    const float* bhh1  = (const float*)d_in[8];
    float* out = (float*)d_out;

    int dev = 0;
    cudaGetDevice(&dev);
    int G = 0;
    cudaDeviceGetAttribute(&G, cudaDevAttrMultiProcessorCount, dev);
    if (G <= 0) G = 148;
    if (G > 1024) G = 1024;

    static int smem_set = 0;
    if (!smem_set) {
        cudaFuncSetAttribute(lstm_seq, cudaFuncAttributeMaxDynamicSharedMemorySize,
                             SMEM_BYTES);
        smem_set = 1;
    }

    int pro_blocks = CVT_BLOCKS + (FOURH / 64) * ((NS + 63) / 64);
    prologue<<<pro_blocks, 256>>>(batch, Wih0, bih0, bhh0, Whh0, Wih1, Whh1);

    lstm_seq<<<G, 1024, SMEM_BYTES>>>(bih1, bhh1, out, G);
}

// round 16
// speedup vs baseline: 2.1753x; 1.1907x over previous
#include <cuda_runtime.h>
#include <cuda_fp16.h>
#include <cstdint>

#define Hd     1536
#define FOURH  6144
#define NS     1008      // (T-1)*B = 63*16 sequential steps
#define CHUNKS 6         // 1536 / 256
#define SC     3         // chunks cached in smem per warp

// ---------------- static device scratch ----------------
__device__ float  g_xpre[(size_t)NS * FOURH];       // layer-0 input projection
__device__ __align__(16) __half g_Whh0h[(size_t)FOURH * Hd];  // fp16, lane-permuted
__device__ __align__(16) __half g_Wih1h[(size_t)FOURH * Hd];
__device__ __align__(16) __half g_Whh1h[(size_t)FOURH * Hd];
__device__ float  g_h0[2][Hd];
__device__ float  g_h1[2][Hd];
__device__ float  g_pa[2][FOURH];
__device__ unsigned int g_bar_count = 0;
__device__ __align__(256) unsigned int g_gen8[8 * 64];   // 8 release words, 256B apart

// dyn smem: [ sh0:1536 f32 | sh1:1536 f32 | wcache: 32 warps * 6KB ]
#define WC_PER_WARP (SC * 4 * 256)                 // halves
#define SMEM_BYTES  (2 * Hd * 4 + 32 * WC_PER_WARP * 2)

// ---------------- software grid barrier: flat atomic arrival, 8-way fanned release --
// Identical to the proven R5 barrier except the single release word becomes 8
// words on distinct LTS slices; block b polls word (b&7) -> ~19 pollers per word
// instead of 151 on one. All 8 words are written together by the releaser, so
// they stay equal; monotonic across graph replays exactly like the R5 original.
__device__ __forceinline__ void grid_barrier(int G) {
    __syncthreads();
    if (threadIdx.x == 0) {
        __threadfence();
        volatile unsigned int* myg = &g_gen8[(blockIdx.x & 7) * 64];
        unsigned int gen = *myg;
        unsigned int a = atomicAdd(&g_bar_count, 1u);
        if (a == (unsigned int)(G - 1)) {
            atomicExch(&g_bar_count, 0u);
            __threadfence();
#pragma unroll
            for (int k = 0; k < 8; k++)
                ((volatile unsigned int*)g_gen8)[k * 64] = gen + 1u;
        } else {
            while (*myg == gen) { }
        }
    }
    __syncthreads();
}

__device__ __forceinline__ float wred(float v) {
    v += __shfl_xor_sync(0xffffffffu, v, 16);
    v += __shfl_xor_sync(0xffffffffu, v, 8);
    v += __shfl_xor_sync(0xffffffffu, v, 4);
    v += __shfl_xor_sync(0xffffffffu, v, 2);
    v += __shfl_xor_sync(0xffffffffu, v, 1);
    return v;
}

__device__ __forceinline__ float sigm(float x) { return 1.0f / (1.0f + expf(-x)); }

// ---------------- weight conversion fp32 -> fp16 (lane-permuted) ----------------
// Within each 1536-wide row, dst position p = chunk*256 + lane*8 + e holds
// src element chunk*256 + e*32 + lane.
__global__ void convert_weights(const float* __restrict__ Whh0,
                                const float* __restrict__ Wih1,
                                const float* __restrict__ Whh1) {
    size_t idx = (size_t)blockIdx.x * blockDim.x + threadIdx.x;
    const size_t per = (size_t)FOURH * Hd;
    if (idx >= 3 * per) return;
    int which = (int)(idx / per);
    size_t rem = idx % per;
    size_t r = rem / Hd;
    int p = (int)(rem % Hd);
    int chunk = p >> 8, q = p & 255, lane = q >> 3, e = q & 7;
    int srcp = chunk * 256 + e * 32 + lane;
    const float* src = (which == 0) ? Whh0 : (which == 1) ? Wih1 : Whh1;
    __half* dst = (which == 0) ? g_Whh0h : (which == 1) ? g_Wih1h : g_Whh1h;
    dst[r * Hd + p] = __float2half(src[r * Hd + srcp]);
}

// ---------------- Kernel: x_pre0 GEMM ----------------
__global__ void gemm_xpre(const float* __restrict__ batch,
                          const float* __restrict__ Wih0,
                          const float* __restrict__ bih0,
                          const float* __restrict__ bhh0) {
    const int BM = 64, BN = 64, BK = 32;
    __shared__ float Xs[BM][BK + 1];
    __shared__ float Ws[BN][BK + 1];

    int tid = threadIdx.x;
    int nb = blockIdx.x * BN;
    int mb = blockIdx.y * BM;
    int tx = tid % 16, ty = tid / 16;

    float acc[4][4];
#pragma unroll
    for (int i = 0; i < 4; i++)
#pragma unroll
        for (int jj = 0; jj < 4; jj++) acc[i][jj] = 0.0f;

    for (int k0 = 0; k0 < 256; k0 += BK) {
#pragma unroll
        for (int i = 0; i < 8; i++) {
            int idx = tid + i * 256;
            int r = idx >> 5, kk = idx & 31;
            int m = mb + r;
            float v = 0.0f;
            if (m < NS) {
                int ei = m >> 4, bb = m & 15;
                v = batch[(size_t)bb * (64 * 256) + (size_t)(ei + 1) * 256 + (k0 + kk)];
            }
            Xs[r][kk] = v;
        }
#pragma unroll
        for (int i = 0; i < 8; i++) {
            int idx = tid + i * 256;
            int r = idx >> 5, kk = idx & 31;
            Ws[r][kk] = Wih0[(size_t)(nb + r) * 256 + (k0 + kk)];
        }
        __syncthreads();
#pragma unroll
        for (int kk = 0; kk < BK; kk++) {
            float xv[4], wv[4];
#pragma unroll
            for (int i = 0; i < 4; i++) xv[i] = Xs[ty * 4 + i][kk];
#pragma unroll
            for (int jj = 0; jj < 4; jj++) wv[jj] = Ws[tx * 4 + jj][kk];
#pragma unroll
            for (int i = 0; i < 4; i++)
#pragma unroll
                for (int jj = 0; jj < 4; jj++) acc[i][jj] += xv[i] * wv[jj];
        }
        __syncthreads();
    }
#pragma unroll
    for (int i = 0; i < 4; i++) {
        int m = mb + ty * 4 + i;
        if (m >= NS) continue;
#pragma unroll
        for (int jj = 0; jj < 4; jj++) {
            int n = nb + tx * 4 + jj;
            g_xpre[(size_t)m * FOURH + n] = acc[i][jj] + bih0[n] + bhh0[n];
        }
    }
}

// ---------------- one 256-wide chunk: 4 gate rows ----------------
// Lane's uint4 at p + lane*8 halves: contiguous 512B per segment -> conflict-free.
__device__ __forceinline__ void mv_chunk4(const __half* p0, const __half* p1,
                                          const __half* p2, const __half* p3,
                                          const float* __restrict__ sh, int kbase,
                                          int lane, float acc[4]) {
    float hv0 = sh[kbase + lane +   0], hv1 = sh[kbase + lane +  32];
    float hv2 = sh[kbase + lane +  64], hv3 = sh[kbase + lane +  96];
    float hv4 = sh[kbase + lane + 128], hv5 = sh[kbase + lane + 160];
    float hv6 = sh[kbase + lane + 192], hv7 = sh[kbase + lane + 224];
#pragma unroll
    for (int t = 0; t < 4; t++) {
        const __half* rp = (t == 0) ? p0 : (t == 1) ? p1 : (t == 2) ? p2 : p3;
        uint4 u = *(const uint4*)(rp + lane * 8);
        const __half2* h2 = (const __half2*)&u;
        float2 f0 = __half22float2(h2[0]);
        float2 f1 = __half22float2(h2[1]);
        float2 f2 = __half22float2(h2[2]);
        float2 f3 = __half22float2(h2[3]);
        acc[t] += f0.x * hv0 + f0.y * hv1 + f1.x * hv2 + f1.y * hv3
                + f2.x * hv4 + f2.y * hv5 + f3.x * hv6 + f3.y * hv7;
    }
}

// full 1536-wide 4-row matvec: chunks 0..SC-1 from smem cache, SC..5 from L2
__device__ __forceinline__ void mv4_hybrid(const __half* __restrict__ scache,
                                           const __half* __restrict__ gW, int j,
                                           const float* __restrict__ sh, int lane,
                                           float acc[4]) {
    const __half* r0 = gW + (size_t)(0 * Hd + j) * Hd;
    const __half* r1 = gW + (size_t)(1 * Hd + j) * Hd;
    const __half* r2 = gW + (size_t)(2 * Hd + j) * Hd;
    const __half* r3 = gW + (size_t)(3 * Hd + j) * Hd;
#pragma unroll
    for (int cc = 0; cc < SC; cc++) {
        const __half* base = scache + cc * 4 * 256;
        mv_chunk4(base + 0 * 256, base + 1 * 256, base + 2 * 256, base + 3 * 256,
                  sh, cc * 256, lane, acc);
    }
#pragma unroll
    for (int cc = SC; cc < CHUNKS; cc++) {
        mv_chunk4(r0 + cc * 256, r1 + cc * 256, r2 + cc * 256, r3 + cc * 256,
                  sh, cc * 256, lane, acc);
    }
}

// ---------------- persistent sequential LSTM ----------------
// Iteration it:
//   L0 warps: h0(it) from h0(it-1)                         [it < NS]
//   A  warps: pa(it-1) = Wih1 . h0(it-1)                   [1 <= it <= NS]
//   B  warps: finalize step it-2: Whh1 . h1(it-3) + pa     [it >= 2]
__global__ __launch_bounds__(1024, 1)
void lstm_seq(const float* __restrict__ bih1,
              const float* __restrict__ bhh1,
              float* __restrict__ out,
              int G) {
    extern __shared__ unsigned char dynsmem[];
    float*  sh0    = (float*)dynsmem;               // 1536 f32
    float*  sh1    = sh0 + Hd;                      // 1536 f32
    __half* wcache = (__half*)(sh1 + Hd);           // 32 * WC_PER_WARP halves

    int tid  = threadIdx.x;
    int b    = blockIdx.x;
    int warp = tid >> 5;
    int lane = tid & 31;

    for (int i = tid; i < Hd; i += 1024) {
        g_h0[0][i] = 0.0f; g_h0[1][i] = 0.0f;
        g_h1[0][i] = 0.0f; g_h1[1][i] = 0.0f;
    }
    for (int i = tid + b * 1024; i < FOURH; i += 1024 * G) {
        g_pa[0][i] = 0.0f; g_pa[1][i] = 0.0f;
    }

    int u = warp * G + b;
    bool isL0 = (u < Hd);
    bool isA  = (u >= Hd)     && (u < 2 * Hd);
    bool isB  = (u >= 2 * Hd) && (u < 3 * Hd);
    bool active = isL0 || isA || isB;
    int j = isL0 ? u : isA ? (u - Hd) : (u - 2 * Hd);

    const __half* gW = isL0 ? g_Whh0h : isA ? g_Wih1h : g_Whh1h;
    __half* scache = wcache + (size_t)warp * WC_PER_WARP;

    // fill per-warp smem cache: chunks 0..SC-1, 4 gate segments (conflict-free layout)
    if (active) {
#pragma unroll
        for (int cc = 0; cc < SC; cc++) {
#pragma unroll
            for (int t = 0; t < 4; t++) {
                const __half* src = gW + (size_t)(t * Hd + j) * Hd + cc * 256 + lane * 8;
                __half* dst = scache + (cc * 4 + t) * 256 + lane * 8;
                *(uint4*)dst = *(const uint4*)src;
            }
        }
    }

    float bi = 0.f, bf = 0.f, bg = 0.f, bo = 0.f;
    if (isB) {
        bi = bih1[0 * Hd + j] + bhh1[0 * Hd + j];
        bf = bih1[1 * Hd + j] + bhh1[1 * Hd + j];
        bg = bih1[2 * Hd + j] + bhh1[2 * Hd + j];
        bo = bih1[3 * Hd + j] + bhh1[3 * Hd + j];
    }

    grid_barrier(G);

    float c = 0.0f, h = 0.0f;   // register-resident cell state

    for (int it = 0; it <= NS + 1; ++it) {
        int rp = (it + 1) & 1;   // read parity
        int wp = it & 1;         // write parity

        {
            volatile const float* vh0 = g_h0[rp];
            volatile const float* vh1 = g_h1[rp];
            for (int i = tid; i < Hd; i += 1024) {
                sh0[i] = vh0[i];
                sh1[i] = vh1[i];
            }
        }
        __syncthreads();

        if (isL0) {
            if (it < NS) {
                float acc[4] = {0.f, 0.f, 0.f, 0.f};
                mv4_hybrid(scache, gW, j, sh0, lane, acc);
                float pi = wred(acc[0]);
                float pf = wred(acc[1]);
                float pg = wred(acc[2]);
                float po = wred(acc[3]);
                const float* xp = g_xpre + (size_t)it * FOURH;
                pi += xp[0 * Hd + j];
                pf += xp[1 * Hd + j];
                pg += xp[2 * Hd + j];
                po += xp[3 * Hd + j];
                c = sigm(pf) * c + sigm(pi) * tanhf(pg);
                h = sigm(po) * tanhf(c);
                if (lane == 0) ((volatile float*)g_h0[wp])[j] = h;
            }
        } else if (isA) {
            if (it >= 1 && it <= NS) {
                float acc[4] = {0.f, 0.f, 0.f, 0.f};
                mv4_hybrid(scache, gW, j, sh0, lane, acc);
                float pi = wred(acc[0]);
                float pf = wred(acc[1]);
                float pg = wred(acc[2]);
                float po = wred(acc[3]);
                if (lane == 0) {
                    volatile float* pa = g_pa[wp];
                    pa[0 * Hd + j] = pi;
                    pa[1 * Hd + j] = pf;
                    pa[2 * Hd + j] = pg;
                    pa[3 * Hd + j] = po;
                }
            }
        } else if (isB) {
            if (it >= 2) {
                float acc[4] = {0.f, 0.f, 0.f, 0.f};
                mv4_hybrid(scache, gW, j, sh1, lane, acc);
                float pi = wred(acc[0]);
                float pf = wred(acc[1]);
                float pg = wred(acc[2]);
                float po = wred(acc[3]);
                if (lane == 0) {
                    volatile const float* pa = g_pa[rp];   // written at it-1
                    pi += pa[0 * Hd + j] + bi;
                    pf += pa[1 * Hd + j] + bf;
                    pg += pa[2 * Hd + j] + bg;
                    po += pa[3 * Hd + j] + bo;
                    c = sigm(pf) * c + sigm(pi) * tanhf(pg);
                    h = sigm(po) * tanhf(c);
                    ((volatile float*)g_h1[wp])[j] = h;
                }
            }
        }

        __threadfence();
        grid_barrier(G);
    }

    // out layout: [h0 | h1 | c0 | c1]
    if (lane == 0) {
        if (isL0) { out[j] = h;      out[2 * Hd + j] = c; }
        if (isB)  { out[Hd + j] = h; out[3 * Hd + j] = c; }
    }
}

// ---------------- launch ----------------
extern "C" void kernel_launch(void* const* d_in, const int* in_sizes, int n_in,
                              void* d_out, int out_size) {
    const float* batch = (const float*)d_in[0];
    const float* Wih0  = (const float*)d_in[1];
    const float* Whh0  = (const float*)d_in[2];
    const float* bih0  = (const float*)d_in[3];
    const float* bhh0  = (const float*)d_in[4];
    const float* Wih1  = (const float*)d_in[5];
    const float* Whh1  = (const float*)d_in[6];
    const float* bih1  = (const float*)d_in[7];
    const float* bhh1  = (const float*)d_in[8];
    float* out = (float*)d_out;

    int dev = 0;
    cudaGetDevice(&dev);
    int G = 0;
    cudaDeviceGetAttribute(&G, cudaDevAttrMultiProcessorCount, dev);
    if (G <= 0) G = 148;

    static int smem_set = 0;
    if (!smem_set) {
        cudaFuncSetAttribute(lstm_seq, cudaFuncAttributeMaxDynamicSharedMemorySize,
                             SMEM_BYTES);
        smem_set = 1;
    }

    size_t total = (size_t)3 * FOURH * Hd;
    int cvt_blocks = (int)((total + 255) / 256);
    convert_weights<<<cvt_blocks, 256>>>(Whh0, Wih1, Whh1);

    dim3 g1(FOURH / 64, (NS + 63) / 64);
    gemm_xpre<<<g1, 256>>>(batch, Wih0, bih0, bhh0);

    lstm_seq<<<G, 1024, SMEM_BYTES>>>(bih1, bhh1, out, G);
}

// round 17
// speedup vs baseline: 2.2722x; 1.0445x over previous
#include <cuda_runtime.h>
#include <cuda_fp16.h>
#include <cstdint>

#define Hd     1536
#define FOURH  6144
#define NS     1008      // (T-1)*B = 63*16 sequential steps
#define CHUNKS 6         // 1536 / 256
#define SC     3         // chunks cached in smem per warp

// ---------------- static device scratch ----------------
__device__ float  g_xpre[(size_t)NS * FOURH];       // layer-0 input projection
__device__ __align__(16) __half g_Whh0h[(size_t)FOURH * Hd];  // fp16, lane-permuted
__device__ __align__(16) __half g_Wih1h[(size_t)FOURH * Hd];
__device__ __align__(16) __half g_Whh1h[(size_t)FOURH * Hd];
__device__ float  g_h0[2][Hd];
__device__ float  g_h1[2][Hd];
__device__ float  g_pa[2][FOURH];
__device__ unsigned int g_bar_count = 0;                 // monotonic within a launch
__device__ __align__(256) unsigned int g_gen8[8 * 64];   // 8 release words, 256B apart
// Barrier state zeroed by convert_weights block 0 each launch (stream-ordered
// before lstm_seq) -> launch-local, capture/replay-safe.

// dyn smem: [ sh0:1536 f32 | sh1:1536 f32 | wcache: 32 warps * 6KB ]
#define WC_PER_WARP (SC * 4 * 256)                 // halves
#define SMEM_BYTES  (2 * Hd * 4 + 32 * WC_PER_WARP * 2)

// ---------------- grid barrier: flat monotonic arrival, 8-way fanned release --------
// Barrier #n (n = 1..K within launch): block arrives via atomicAdd on a single
// monotonic counter (no reset on the release path); the block seeing
// a == n*G-1 is last and writes n into 8 release words on distinct LTS slices.
// Block b polls word (b&7). Thread-0 fence after syncthreads is cumulative for
// the whole block's prior writes (cg grid-sync pattern).
__device__ __forceinline__ void grid_barrier(int G, unsigned int n) {
    __syncthreads();
    if (threadIdx.x == 0) {
        __threadfence();
        volatile unsigned int* myg = &g_gen8[(blockIdx.x & 7) * 64];
        unsigned int a = atomicAdd(&g_bar_count, 1u);
        if (a == n * (unsigned int)G - 1u) {
            __threadfence();
#pragma unroll
            for (int k = 0; k < 8; k++)
                ((volatile unsigned int*)g_gen8)[k * 64] = n;
        } else {
            while (*myg < n) { }
        }
        __threadfence();
    }
    __syncthreads();
}

__device__ __forceinline__ float wred(float v) {
    v += __shfl_xor_sync(0xffffffffu, v, 16);
    v += __shfl_xor_sync(0xffffffffu, v, 8);
    v += __shfl_xor_sync(0xffffffffu, v, 4);
    v += __shfl_xor_sync(0xffffffffu, v, 2);
    v += __shfl_xor_sync(0xffffffffu, v, 1);
    return v;
}

// fast epilogue transcendentals (MUFU.EX2 path; ~1e-6 rel err)
__device__ __forceinline__ float sigm(float x) {
    return __fdividef(1.0f, 1.0f + __expf(-x));
}
__device__ __forceinline__ float tanhfast(float x) {
    // 1 - 2/(e^{2x}+1); __expf saturates to +inf/0 -> correct +/-1 limits
    return 1.0f - __fdividef(2.0f, __expf(2.0f * x) + 1.0f);
}

// ---------------- weight conversion fp32 -> fp16 (lane-permuted) + barrier reset -----
// Within each 1536-wide row, dst position p = chunk*256 + lane*8 + e holds
// src element chunk*256 + e*32 + lane.
__global__ void convert_weights(const float* __restrict__ Whh0,
                                const float* __restrict__ Wih1,
                                const float* __restrict__ Whh1) {
    if (blockIdx.x == 0) {   // reset barrier state for the upcoming lstm_seq launch
        if (threadIdx.x == 0) g_bar_count = 0u;
        for (int i = threadIdx.x; i < 8 * 64; i += blockDim.x) g_gen8[i] = 0u;
    }
    size_t idx = (size_t)blockIdx.x * blockDim.x + threadIdx.x;
    const size_t per = (size_t)FOURH * Hd;
    if (idx >= 3 * per) return;
    int which = (int)(idx / per);
    size_t rem = idx % per;
    size_t r = rem / Hd;
    int p = (int)(rem % Hd);
    int chunk = p >> 8, q = p & 255, lane = q >> 3, e = q & 7;
    int srcp = chunk * 256 + e * 32 + lane;
    const float* src = (which == 0) ? Whh0 : (which == 1) ? Wih1 : Whh1;
    __half* dst = (which == 0) ? g_Whh0h : (which == 1) ? g_Wih1h : g_Whh1h;
    dst[r * Hd + p] = __float2half(src[r * Hd + srcp]);
}

// ---------------- Kernel: x_pre0 GEMM ----------------
__global__ void gemm_xpre(const float* __restrict__ batch,
                          const float* __restrict__ Wih0,
                          const float* __restrict__ bih0,
                          const float* __restrict__ bhh0) {
    const int BM = 64, BN = 64, BK = 32;
    __shared__ float Xs[BM][BK + 1];
    __shared__ float Ws[BN][BK + 1];

    int tid = threadIdx.x;
    int nb = blockIdx.x * BN;
    int mb = blockIdx.y * BM;
    int tx = tid % 16, ty = tid / 16;

    float acc[4][4];
#pragma unroll
    for (int i = 0; i < 4; i++)
#pragma unroll
        for (int jj = 0; jj < 4; jj++) acc[i][jj] = 0.0f;

    for (int k0 = 0; k0 < 256; k0 += BK) {
#pragma unroll
        for (int i = 0; i < 8; i++) {
            int idx = tid + i * 256;
            int r = idx >> 5, kk = idx & 31;
            int m = mb + r;
            float v = 0.0f;
            if (m < NS) {
                int ei = m >> 4, bb = m & 15;
                v = batch[(size_t)bb * (64 * 256) + (size_t)(ei + 1) * 256 + (k0 + kk)];
            }
            Xs[r][kk] = v;
        }
#pragma unroll
        for (int i = 0; i < 8; i++) {
            int idx = tid + i * 256;
            int r = idx >> 5, kk = idx & 31;
            Ws[r][kk] = Wih0[(size_t)(nb + r) * 256 + (k0 + kk)];
        }
        __syncthreads();
#pragma unroll
        for (int kk = 0; kk < BK; kk++) {
            float xv[4], wv[4];
#pragma unroll
            for (int i = 0; i < 4; i++) xv[i] = Xs[ty * 4 + i][kk];
#pragma unroll
            for (int jj = 0; jj < 4; jj++) wv[jj] = Ws[tx * 4 + jj][kk];
#pragma unroll
            for (int i = 0; i < 4; i++)
#pragma unroll
                for (int jj = 0; jj < 4; jj++) acc[i][jj] += xv[i] * wv[jj];
        }
        __syncthreads();
    }
#pragma unroll
    for (int i = 0; i < 4; i++) {
        int m = mb + ty * 4 + i;
        if (m >= NS) continue;
#pragma unroll
        for (int jj = 0; jj < 4; jj++) {
            int n = nb + tx * 4 + jj;
            g_xpre[(size_t)m * FOURH + n] = acc[i][jj] + bih0[n] + bhh0[n];
        }
    }
}

// ---------------- one 256-wide chunk: 4 gate rows ----------------
__device__ __forceinline__ void mv_chunk4(const __half* p0, const __half* p1,
                                          const __half* p2, const __half* p3,
                                          const float* __restrict__ sh, int kbase,
                                          int lane, float acc[4]) {
    float hv0 = sh[kbase + lane +   0], hv1 = sh[kbase + lane +  32];
    float hv2 = sh[kbase + lane +  64], hv3 = sh[kbase + lane +  96];
    float hv4 = sh[kbase + lane + 128], hv5 = sh[kbase + lane + 160];
    float hv6 = sh[kbase + lane + 192], hv7 = sh[kbase + lane + 224];
#pragma unroll
    for (int t = 0; t < 4; t++) {
        const __half* rp = (t == 0) ? p0 : (t == 1) ? p1 : (t == 2) ? p2 : p3;
        uint4 u = *(const uint4*)(rp + lane * 8);
        const __half2* h2 = (const __half2*)&u;
        float2 f0 = __half22float2(h2[0]);
        float2 f1 = __half22float2(h2[1]);
        float2 f2 = __half22float2(h2[2]);
        float2 f3 = __half22float2(h2[3]);
        acc[t] += f0.x * hv0 + f0.y * hv1 + f1.x * hv2 + f1.y * hv3
                + f2.x * hv4 + f2.y * hv5 + f3.x * hv6 + f3.y * hv7;
    }
}

// full 1536-wide 4-row matvec: chunks 0..SC-1 from smem cache, SC..5 from L2
__device__ __forceinline__ void mv4_hybrid(const __half* __restrict__ scache,
                                           const __half* __restrict__ gW, int j,
                                           const float* __restrict__ sh, int lane,
                                           float acc[4]) {
    const __half* r0 = gW + (size_t)(0 * Hd + j) * Hd;
    const __half* r1 = gW + (size_t)(1 * Hd + j) * Hd;
    const __half* r2 = gW + (size_t)(2 * Hd + j) * Hd;
    const __half* r3 = gW + (size_t)(3 * Hd + j) * Hd;
#pragma unroll
    for (int cc = 0; cc < SC; cc++) {
        const __half* base = scache + cc * 4 * 256;
        mv_chunk4(base + 0 * 256, base + 1 * 256, base + 2 * 256, base + 3 * 256,
                  sh, cc * 256, lane, acc);
    }
#pragma unroll
    for (int cc = SC; cc < CHUNKS; cc++) {
        mv_chunk4(r0 + cc * 256, r1 + cc * 256, r2 + cc * 256, r3 + cc * 256,
                  sh, cc * 256, lane, acc);
    }
}

// ---------------- persistent sequential LSTM ----------------
// Iteration it:
//   L0 warps: h0(it) from h0(it-1)                         [it < NS]
//   A  warps: pa(it-1) = Wih1 . h0(it-1)                   [1 <= it <= NS]
//   B  warps: finalize step it-2: Whh1 . h1(it-3) + pa     [it >= 2]
__global__ __launch_bounds__(1024, 1)
void lstm_seq(const float* __restrict__ bih1,
              const float* __restrict__ bhh1,
              float* __restrict__ out,
              int G) {
    extern __shared__ unsigned char dynsmem[];
    float*  sh0    = (float*)dynsmem;               // 1536 f32
    float*  sh1    = sh0 + Hd;                      // 1536 f32
    __half* wcache = (__half*)(sh1 + Hd);           // 32 * WC_PER_WARP halves

    int tid  = threadIdx.x;
    int b    = blockIdx.x;
    int warp = tid >> 5;
    int lane = tid & 31;

    unsigned int bar_n = 0;   // launch-local barrier sequence

    for (int i = tid; i < Hd; i += 1024) {
        g_h0[0][i] = 0.0f; g_h0[1][i] = 0.0f;
        g_h1[0][i] = 0.0f; g_h1[1][i] = 0.0f;
    }
    for (int i = tid + b * 1024; i < FOURH; i += 1024 * G) {
        g_pa[0][i] = 0.0f; g_pa[1][i] = 0.0f;
    }

    int u = warp * G + b;
    bool isL0 = (u < Hd);
    bool isA  = (u >= Hd)     && (u < 2 * Hd);
    bool isB  = (u >= 2 * Hd) && (u < 3 * Hd);
    bool active = isL0 || isA || isB;
    int j = isL0 ? u : isA ? (u - Hd) : (u - 2 * Hd);

    const __half* gW = isL0 ? g_Whh0h : isA ? g_Wih1h : g_Whh1h;
    __half* scache = wcache + (size_t)warp * WC_PER_WARP;

    // fill per-warp smem cache: chunks 0..SC-1, 4 gate segments (conflict-free layout)
    if (active) {
#pragma unroll
        for (int cc = 0; cc < SC; cc++) {
#pragma unroll
            for (int t = 0; t < 4; t++) {
                const __half* src = gW + (size_t)(t * Hd + j) * Hd + cc * 256 + lane * 8;
                __half* dst = scache + (cc * 4 + t) * 256 + lane * 8;
                *(uint4*)dst = *(const uint4*)src;
            }
        }
    }

    float bi = 0.f, bf = 0.f, bg = 0.f, bo = 0.f;
    if (isB) {
        bi = bih1[0 * Hd + j] + bhh1[0 * Hd + j];
        bf = bih1[1 * Hd + j] + bhh1[1 * Hd + j];
        bg = bih1[2 * Hd + j] + bhh1[2 * Hd + j];
        bo = bih1[3 * Hd + j] + bhh1[3 * Hd + j];
    }

    grid_barrier(G, ++bar_n);

    float c = 0.0f, h = 0.0f;   // register-resident cell state

    for (int it = 0; it <= NS + 1; ++it) {
        int rp = (it + 1) & 1;   // read parity
        int wp = it & 1;         // write parity

        // ---- hoisted loads independent of staged h (latency hides under staging) ----
        float xpi = 0.f, xpf = 0.f, xpg = 0.f, xpo = 0.f;
        if (isL0 && it < NS) {
            const float* xp = g_xpre + (size_t)it * FOURH;
            xpi = xp[0 * Hd + j];
            xpf = xp[1 * Hd + j];
            xpg = xp[2 * Hd + j];
            xpo = xp[3 * Hd + j];
        }
        float pai = 0.f, paf = 0.f, pag = 0.f, pao = 0.f;
        if (isB && it >= 2) {
            volatile const float* pa = g_pa[rp];   // written at it-1
            pai = pa[0 * Hd + j];
            paf = pa[1 * Hd + j];
            pag = pa[2 * Hd + j];
            pao = pa[3 * Hd + j];
        }

        // ---- stage previous h vectors into smem (fp32) ----
        {
            volatile const float* vh0 = g_h0[rp];
            volatile const float* vh1 = g_h1[rp];
            for (int i = tid; i < Hd; i += 1024) {
                sh0[i] = vh0[i];
                sh1[i] = vh1[i];
            }
        }
        __syncthreads();

        if (isL0) {
            if (it < NS) {
                float acc[4] = {0.f, 0.f, 0.f, 0.f};
                mv4_hybrid(scache, gW, j, sh0, lane, acc);
                float pi = wred(acc[0]) + xpi;
                float pf = wred(acc[1]) + xpf;
                float pg = wred(acc[2]) + xpg;
                float po = wred(acc[3]) + xpo;
                c = sigm(pf) * c + sigm(pi) * tanhfast(pg);
                h = sigm(po) * tanhfast(c);
                if (lane == 0) ((volatile float*)g_h0[wp])[j] = h;
            }
        } else if (isA) {
            if (it >= 1 && it <= NS) {
                float acc[4] = {0.f, 0.f, 0.f, 0.f};
                mv4_hybrid(scache, gW, j, sh0, lane, acc);
                float pi = wred(acc[0]);
                float pf = wred(acc[1]);
                float pg = wred(acc[2]);
                float po = wred(acc[3]);
                if (lane == 0) {
                    volatile float* pa = g_pa[wp];
                    pa[0 * Hd + j] = pi;
                    pa[1 * Hd + j] = pf;
                    pa[2 * Hd + j] = pg;
                    pa[3 * Hd + j] = po;
                }
            }
        } else if (isB) {
            if (it >= 2) {
                float acc[4] = {0.f, 0.f, 0.f, 0.f};
                mv4_hybrid(scache, gW, j, sh1, lane, acc);
                float pi = wred(acc[0]) + pai + bi;
                float pf = wred(acc[1]) + paf + bf;
                float pg = wred(acc[2]) + pag + bg;
                float po = wred(acc[3]) + pao + bo;
                if (lane == 0) {
                    c = sigm(pf) * c + sigm(pi) * tanhfast(pg);
                    h = sigm(po) * tanhfast(c);
                    ((volatile float*)g_h1[wp])[j] = h;
                }
            }
        }

        grid_barrier(G, ++bar_n);
    }

    // out layout: [h0 | h1 | c0 | c1]
    if (lane == 0) {
        if (isL0) { out[j] = h;      out[2 * Hd + j] = c; }
        if (isB)  { out[Hd + j] = h; out[3 * Hd + j] = c; }
    }
}

// ---------------- launch ----------------
extern "C" void kernel_launch(void* const* d_in, const int* in_sizes, int n_in,
                              void* d_out, int out_size) {
    const float* batch = (const float*)d_in[0];
    const float* Wih0  = (const float*)d_in[1];
    const float* Whh0  = (const float*)d_in[2];
    const float* bih0  = (const float*)d_in[3];
    const float* bhh0  = (const float*)d_in[4];
    const float* Wih1  = (const float*)d_in[5];
    const float* Whh1  = (const float*)d_in[6];
    const float* bih1  = (const float*)d_in[7];
    const float* bhh1  = (const float*)d_in[8];
    float* out = (float*)d_out;

    int dev = 0;
    cudaGetDevice(&dev);
    int G = 0;
    cudaDeviceGetAttribute(&G, cudaDevAttrMultiProcessorCount, dev);
    if (G <= 0) G = 148;

    static int smem_set = 0;
    if (!smem_set) {
        cudaFuncSetAttribute(lstm_seq, cudaFuncAttributeMaxDynamicSharedMemorySize,
                             SMEM_BYTES);
        smem_set = 1;
    }

    size_t total = (size_t)3 * FOURH * Hd;
    int cvt_blocks = (int)((total + 255) / 256);
    convert_weights<<<cvt_blocks, 256>>>(Whh0, Wih1, Whh1);

    dim3 g1(FOURH / 64, (NS + 63) / 64);
    gemm_xpre<<<g1, 256>>>(batch, Wih0, bih0, bhh0);

    lstm_seq<<<G, 1024, SMEM_BYTES>>>(bih1, bhh1, out, G);
}